// round 8
// baseline (speedup 1.0000x reference)
#include <cuda_runtime.h>
#include <cstdint>

#define N_NODES_MAX 100000
#define N_EDGES_MAX 600000

// Scratch (device globals)
__device__ __align__(16) float g_xsum[(size_t)N_NODES_MAX * 128];  // xsum; reused as 'a'
__device__ __align__(16) float g_h1  [(size_t)N_NODES_MAX * 128];  // layer-1 out; reused as 'b'
__device__ __align__(16) float g_h2  [(size_t)N_NODES_MAX * 128];  // layer-2 out
__device__ __align__(16) float g_eagg[(size_t)N_NODES_MAX * 32];   // sum of edge_attr per dst
__device__ __align__(16) float g_inv [N_NODES_MAX];                // 1/max(deg,1)
__device__ __align__(16) float g_degc[N_NODES_MAX];                // deg>0 ? 1 : 0
__device__ __align__(16) float g_P   [2 * 32 * 128];               // We_l @ Wl_l
__device__ __align__(16) float g_bv1 [2 * 128];                    // be_l @ Wl_l
__device__ __align__(16) float g_bv0 [2 * 128];                    // bl_l + br_l
// CSR (built per launch)
__device__ int g_rowptr[N_NODES_MAX + 1];
__device__ int g_cnt   [N_NODES_MAX];
__device__ int g_bsum  [1024];
__device__ int g_boff  [1024];
__device__ int g_csr_src[N_EDGES_MAX];
__device__ int g_csr_eid[N_EDGES_MAX];

// ---------------------------------------------------------------------------
// helpers
// ---------------------------------------------------------------------------
__device__ __forceinline__ uint32_t to_tf32(float v) {
    uint32_t u;
    asm("cvt.rna.tf32.f32 %0, %1;" : "=r"(u) : "f"(v));
    return u;
}
__device__ __forceinline__ void mma_tf32(float c[4], const uint32_t a[4],
                                         uint32_t b0, uint32_t b1) {
    asm("mma.sync.aligned.m16n8k8.row.col.f32.tf32.tf32.f32 "
        "{%0,%1,%2,%3}, {%4,%5,%6,%7}, {%8,%9}, {%0,%1,%2,%3};"
        : "+f"(c[0]), "+f"(c[1]), "+f"(c[2]), "+f"(c[3])
        : "r"(a[0]), "r"(a[1]), "r"(a[2]), "r"(a[3]), "r"(b0), "r"(b1));
}

// ---------------------------------------------------------------------------
// CSR build
// ---------------------------------------------------------------------------
__global__ void k_zero_int(int* __restrict__ p, int n) {
    int i = blockIdx.x * blockDim.x + threadIdx.x;
    if (i < n) p[i] = 0;
}

__global__ void k_hist(const int* __restrict__ ei, int* __restrict__ cnt, int E, int N) {
    int e = blockIdx.x * blockDim.x + threadIdx.x;
    if (e < E) {
        int d = ei[E + e];
        if ((unsigned)d < (unsigned)N) atomicAdd(&cnt[d], 1);
    }
}

__global__ void k_scan1(const int* __restrict__ cnt, int* __restrict__ rowptr,
                        int* __restrict__ bsum, int N) {
    __shared__ int sm[512];
    int t = threadIdx.x, b = blockIdx.x, i = b * 512 + t;
    int v = (i < N) ? cnt[i] : 0;
    sm[t] = v;
    __syncthreads();
    #pragma unroll
    for (int off = 1; off < 512; off <<= 1) {
        int add = (t >= off) ? sm[t - off] : 0;
        __syncthreads();
        sm[t] += add;
        __syncthreads();
    }
    if (i < N) rowptr[i + 1] = sm[t];
    if (t == 511) bsum[b] = sm[511];
}

__global__ void k_scan2(const int* __restrict__ bsum, int* __restrict__ boff, int nb) {
    __shared__ int sm[1024];
    int t = threadIdx.x;
    sm[t] = (t < nb) ? bsum[t] : 0;
    __syncthreads();
    #pragma unroll
    for (int off = 1; off < 1024; off <<= 1) {
        int add = (t >= off) ? sm[t - off] : 0;
        __syncthreads();
        sm[t] += add;
        __syncthreads();
    }
    if (t < nb) boff[t] = (t == 0) ? 0 : sm[t - 1];
}

__global__ void k_scan3(int* __restrict__ rowptr, const int* __restrict__ boff,
                        int* __restrict__ cnt, int N) {
    int t = threadIdx.x, b = blockIdx.x, i = b * 512 + t;
    if (i < N) {
        rowptr[i + 1] += boff[b];
        cnt[i] = 0;
        if (i == 0) rowptr[0] = 0;
    }
}

__global__ void k_invdeg(const int* __restrict__ rowptr, float* __restrict__ inv,
                         float* __restrict__ degc, int N) {
    int i = blockIdx.x * blockDim.x + threadIdx.x;
    if (i < N) {
        int deg = rowptr[i + 1] - rowptr[i];
        degc[i] = deg > 0 ? 1.f : 0.f;
        inv[i] = 1.f / fmaxf((float)deg, 1.f);
    }
}

__global__ void k_fill(const int* __restrict__ ei, const int* __restrict__ rowptr,
                       int* __restrict__ cnt, int* __restrict__ csr_src,
                       int* __restrict__ csr_eid, int E, int N) {
    int e = blockIdx.x * blockDim.x + threadIdx.x;
    if (e < E) {
        int s = ei[e];
        int d = ei[E + e];
        if ((unsigned)d < (unsigned)N) {
            int pos = rowptr[d] + atomicAdd(&cnt[d], 1);
            csr_src[pos] = s;
            csr_eid[pos] = e;
        }
    }
}

// ---------------------------------------------------------------------------
// CSR aggregation: one warp per node, register accumulate, single write.
// Layer 1 also sums edge_attr (eagg).
// ---------------------------------------------------------------------------
__global__ void k_agg_l1(const float* __restrict__ x, const float* __restrict__ ea,
                         const int* __restrict__ rowptr,
                         const int* __restrict__ csr_src, const int* __restrict__ csr_eid,
                         float* __restrict__ xsum, float* __restrict__ eagg, int N) {
    int lane = threadIdx.x & 31;
    int n = (blockIdx.x * blockDim.x + threadIdx.x) >> 5;
    if (n >= N) return;
    int beg = rowptr[n], end = rowptr[n + 1];
    const float4* x4 = (const float4*)x;
    float4 acc = make_float4(0.f, 0.f, 0.f, 0.f);
    float eacc = 0.f;
    int i = beg;
    for (; i + 1 < end; i += 2) {
        int s0 = __ldg(&csr_src[i]),     e0 = __ldg(&csr_eid[i]);
        int s1 = __ldg(&csr_src[i + 1]), e1 = __ldg(&csr_eid[i + 1]);
        float4 v0 = __ldg(x4 + (size_t)s0 * 32 + lane);
        float4 v1 = __ldg(x4 + (size_t)s1 * 32 + lane);
        float w0 = __ldg(&ea[(size_t)e0 * 32 + lane]);
        float w1 = __ldg(&ea[(size_t)e1 * 32 + lane]);
        acc.x += v0.x + v1.x; acc.y += v0.y + v1.y;
        acc.z += v0.z + v1.z; acc.w += v0.w + v1.w;
        eacc += w0 + w1;
    }
    if (i < end) {
        int s0 = __ldg(&csr_src[i]), e0 = __ldg(&csr_eid[i]);
        float4 v0 = __ldg(x4 + (size_t)s0 * 32 + lane);
        float w0 = __ldg(&ea[(size_t)e0 * 32 + lane]);
        acc.x += v0.x; acc.y += v0.y; acc.z += v0.z; acc.w += v0.w;
        eacc += w0;
    }
    ((float4*)xsum)[(size_t)n * 32 + lane] = acc;
    eagg[(size_t)n * 32 + lane] = eacc;
}

__global__ void k_agg_l2(const float* __restrict__ x,
                         const int* __restrict__ rowptr,
                         const int* __restrict__ csr_src,
                         float* __restrict__ xsum, int N) {
    int lane = threadIdx.x & 31;
    int n = (blockIdx.x * blockDim.x + threadIdx.x) >> 5;
    if (n >= N) return;
    int beg = rowptr[n], end = rowptr[n + 1];
    const float4* x4 = (const float4*)x;
    float4 acc = make_float4(0.f, 0.f, 0.f, 0.f);
    int i = beg;
    for (; i + 1 < end; i += 2) {
        int s0 = __ldg(&csr_src[i]);
        int s1 = __ldg(&csr_src[i + 1]);
        float4 v0 = __ldg(x4 + (size_t)s0 * 32 + lane);
        float4 v1 = __ldg(x4 + (size_t)s1 * 32 + lane);
        acc.x += v0.x + v1.x; acc.y += v0.y + v1.y;
        acc.z += v0.z + v1.z; acc.w += v0.w + v1.w;
    }
    if (i < end) {
        int s0 = __ldg(&csr_src[i]);
        float4 v0 = __ldg(x4 + (size_t)s0 * 32 + lane);
        acc.x += v0.x; acc.y += v0.y; acc.z += v0.z; acc.w += v0.w;
    }
    ((float4*)xsum)[(size_t)n * 32 + lane] = acc;
}

// ---------------------------------------------------------------------------
// Precompute P_l = We_l @ Wl_l, bv1_l = be_l @ Wl_l, bv0_l = bl_l + br_l.
// ---------------------------------------------------------------------------
__global__ void k_precompute(const float* We1, const float* be1, const float* Wl1,
                             const float* bl1, const float* br1,
                             const float* We2, const float* be2, const float* Wl2,
                             const float* bl2, const float* br2,
                             float* P, float* bv1, float* bv0) {
    int l = blockIdx.x;
    int j = threadIdx.x;
    const float* We = l ? We2 : We1;
    const float* be = l ? be2 : be1;
    const float* Wl = l ? Wl2 : Wl1;
    const float* bl = l ? bl2 : bl1;
    const float* br = l ? br2 : br1;

    for (int i = 0; i < 32; i++) {
        float acc = 0.f;
        for (int k = 0; k < 128; k++) acc = fmaf(We[i * 128 + k], Wl[k * 128 + j], acc);
        P[l * 4096 + i * 128 + j] = acc;
    }
    float a1 = 0.f;
    for (int k = 0; k < 128; k++) a1 = fmaf(be[k], Wl[k * 128 + j], a1);
    bv1[l * 128 + j] = a1;
    bv0[l * 128 + j] = bl[j] + br[j];
}

// ---------------------------------------------------------------------------
// Tensor-core SAGE node GEMM (tf32 mma.sync m16n8k8):
//   C = act( inv[m]*(A1 @ W1) + inv[m]*(A2 @ P) + B @ W2 + bv0 + degc[m]*bv1 )
// BM=128, BN=128, BK=16. 256 threads = 8 warps in 4x2 (m x n); warp = 32x64.
// A-frag loads (stride 136): word%32 = 8*qid+gid -> conflict-free.
// W-frag loads (stride 129): word%32 = qid+8*gid -> conflict-free.
// ---------------------------------------------------------------------------
__global__ __launch_bounds__(256, 2)
void k_gemm_sage_tc(const float* __restrict__ A1,
                    const float* __restrict__ A2,
                    const float* __restrict__ B,
                    const float* __restrict__ W1,
                    const float* __restrict__ P,
                    const float* __restrict__ W2,
                    const float* __restrict__ bv0,
                    const float* __restrict__ bv1,
                    const float* __restrict__ inv,
                    const float* __restrict__ degc,
                    float* __restrict__ C,
                    int M, int relu) {
    __shared__ uint32_t As[16][136];
    __shared__ uint32_t Ws[16][129];

    const int tid    = threadIdx.x;
    const int lane   = tid & 31;
    const int warp   = tid >> 5;
    const int gid    = lane >> 2;
    const int qid    = lane & 3;
    const int warp_m = warp >> 1;
    const int warp_n = warp & 1;
    const int m0     = blockIdx.x * 128;

    float c[2][8][4];
    #pragma unroll
    for (int mt = 0; mt < 2; mt++)
        #pragma unroll
        for (int nt = 0; nt < 8; nt++)
            #pragma unroll
            for (int i = 0; i < 4; i++) c[mt][nt][i] = 0.f;

    const int ktiles = (A2 != nullptr) ? 18 : 8;

    for (int kt = 0; kt < ktiles; kt++) {
        const float* Ain;
        const float* Win;
        int kb, astride;
        bool scaled;
        if (kt < 8)       { Ain = A1; Win = W1; kb = kt * 16;        astride = 128; scaled = (inv != nullptr); }
        else if (kt < 10) { Ain = A2; Win = P;  kb = (kt - 8) * 16;  astride = 32;  scaled = (inv != nullptr); }
        else              { Ain = B;  Win = W2; kb = (kt - 10) * 16; astride = 128; scaled = false; }

        #pragma unroll
        for (int i = 0; i < 8; i++) {
            int lin = tid + i * 256;
            int m = lin >> 4;
            int k = lin & 15;
            int gm = m0 + m;
            float v = 0.f;
            if (gm < M) {
                v = Ain[(size_t)gm * astride + kb + k];
                if (scaled) v *= inv[gm];
            }
            As[k][m] = to_tf32(v);
        }
        #pragma unroll
        for (int i = 0; i < 8; i++) {
            int lin = tid + i * 256;
            int k = lin >> 7;
            int j = lin & 127;
            Ws[k][j] = to_tf32(Win[(size_t)(kb + k) * 128 + j]);
        }
        __syncthreads();

        #pragma unroll
        for (int ks = 0; ks < 2; ks++) {
            const int k8 = ks * 8;
            uint32_t a[2][4];
            #pragma unroll
            for (int mt = 0; mt < 2; mt++) {
                int row = warp_m * 32 + mt * 16 + gid;
                a[mt][0] = As[k8 + qid][row];
                a[mt][1] = As[k8 + qid][row + 8];
                a[mt][2] = As[k8 + qid + 4][row];
                a[mt][3] = As[k8 + qid + 4][row + 8];
            }
            #pragma unroll
            for (int nt = 0; nt < 8; nt++) {
                int col = warp_n * 64 + nt * 8 + gid;
                uint32_t b0 = Ws[k8 + qid][col];
                uint32_t b1 = Ws[k8 + qid + 4][col];
                mma_tf32(c[0][nt], a[0], b0, b1);
                mma_tf32(c[1][nt], a[1], b0, b1);
            }
        }
        __syncthreads();
    }

    #pragma unroll
    for (int mt = 0; mt < 2; mt++) {
        int rbase = m0 + warp_m * 32 + mt * 16 + gid;
        #pragma unroll
        for (int h = 0; h < 2; h++) {
            int r = rbase + h * 8;
            if (r >= M) continue;
            float coef = (bv1 && degc) ? degc[r] : 0.f;
            #pragma unroll
            for (int nt = 0; nt < 8; nt++) {
                int j = warp_n * 64 + nt * 8 + qid * 2;
                float v0 = c[mt][nt][h * 2 + 0];
                float v1 = c[mt][nt][h * 2 + 1];
                if (bv0) { v0 += bv0[j]; v1 += bv0[j + 1]; }
                if (bv1) { v0 += coef * bv1[j]; v1 += coef * bv1[j + 1]; }
                if (relu) { v0 = fmaxf(v0, 0.f); v1 = fmaxf(v1, 0.f); }
                *(float2*)&C[(size_t)r * 128 + j] = make_float2(v0, v1);
            }
        }
    }
}

// ---------------------------------------------------------------------------
// Final edge predictor: out[e] = relu(a[src] + b[dst]) @ Wp2 + bp2
// ---------------------------------------------------------------------------
__global__ void k_edge_final(const float* __restrict__ a,
                             const float* __restrict__ b,
                             const int* __restrict__ ei,
                             const float* __restrict__ Wp2,
                             const float* __restrict__ bp2,
                             float* __restrict__ out,
                             int E, int N) {
    int lane = threadIdx.x & 31;
    int warp = (blockIdx.x * blockDim.x + threadIdx.x) >> 5;
    int nwarp = (gridDim.x * blockDim.x) >> 5;

    float4 w01 = ((const float4*)Wp2)[lane * 2];
    float4 w23 = ((const float4*)Wp2)[lane * 2 + 1];
    float b0 = bp2[0], b1 = bp2[1];

    for (int e = warp; e < E; e += nwarp) {
        int s = ei[e];
        int d = ei[E + e];
        if ((unsigned)s >= (unsigned)N || (unsigned)d >= (unsigned)N) continue;
        float4 av = __ldg((const float4*)a + (size_t)s * 32 + lane);
        float4 bv = __ldg((const float4*)b + (size_t)d * 32 + lane);
        float z0 = fmaxf(av.x + bv.x, 0.f);
        float z1 = fmaxf(av.y + bv.y, 0.f);
        float z2 = fmaxf(av.z + bv.z, 0.f);
        float z3 = fmaxf(av.w + bv.w, 0.f);
        float o0 = z0 * w01.x + z1 * w01.z + z2 * w23.x + z3 * w23.z;
        float o1 = z0 * w01.y + z1 * w01.w + z2 * w23.y + z3 * w23.w;
        #pragma unroll
        for (int off = 16; off > 0; off >>= 1) {
            o0 += __shfl_xor_sync(0xffffffffu, o0, off);
            o1 += __shfl_xor_sync(0xffffffffu, o1, off);
        }
        if (lane == 0) {
            float2 r = make_float2(o0 + b0, o1 + b1);
            *(float2*)&out[(size_t)e * 2] = r;
        }
    }
}

// ---------------------------------------------------------------------------
extern "C" void kernel_launch(void* const* d_in, const int* in_sizes, int n_in,
                              void* d_out, int out_size) {
    const float* x    = (const float*)d_in[0];
    const int*   ei   = (const int*)d_in[1];     // int32
    const float* ea   = (const float*)d_in[2];
    const float* We1  = (const float*)d_in[3];
    const float* be1  = (const float*)d_in[4];
    const float* Wl1  = (const float*)d_in[5];
    const float* bl1  = (const float*)d_in[6];
    const float* Wr1  = (const float*)d_in[7];
    const float* br1  = (const float*)d_in[8];
    const float* We2  = (const float*)d_in[9];
    const float* be2  = (const float*)d_in[10];
    const float* Wl2  = (const float*)d_in[11];
    const float* bl2  = (const float*)d_in[12];
    const float* Wr2  = (const float*)d_in[13];
    const float* br2  = (const float*)d_in[14];
    const float* Wp1  = (const float*)d_in[15];
    const float* bp1  = (const float*)d_in[16];
    const float* Wp2  = (const float*)d_in[17];
    const float* bp2  = (const float*)d_in[18];
    float*       out  = (float*)d_out;

    const int N = in_sizes[0] / 128;
    const int E = in_sizes[2] / 32;

    float *xsum, *h1, *h2, *eagg, *inv, *degc, *P, *bv1, *bv0;
    int *rowptr, *cnt, *bsum, *boff, *csr_src, *csr_eid;
    cudaGetSymbolAddress((void**)&xsum, g_xsum);
    cudaGetSymbolAddress((void**)&h1,   g_h1);
    cudaGetSymbolAddress((void**)&h2,   g_h2);
    cudaGetSymbolAddress((void**)&eagg, g_eagg);
    cudaGetSymbolAddress((void**)&inv,  g_inv);
    cudaGetSymbolAddress((void**)&degc, g_degc);
    cudaGetSymbolAddress((void**)&P,    g_P);
    cudaGetSymbolAddress((void**)&bv1,  g_bv1);
    cudaGetSymbolAddress((void**)&bv0,  g_bv0);
    cudaGetSymbolAddress((void**)&rowptr, g_rowptr);
    cudaGetSymbolAddress((void**)&cnt,    g_cnt);
    cudaGetSymbolAddress((void**)&bsum,   g_bsum);
    cudaGetSymbolAddress((void**)&boff,   g_boff);
    cudaGetSymbolAddress((void**)&csr_src, g_csr_src);
    cudaGetSymbolAddress((void**)&csr_eid, g_csr_eid);

    const int nb    = (N + 511) / 512;           // scan blocks
    const int ggrid = (N + 127) / 128;           // GEMM grid
    const int agrid = (N + 7) / 8;               // warp-per-node grid (256 thr)
    const int egrid = 2368;                      // edge_final grid-stride

    // ---- CSR build ----
    k_zero_int<<<(N + 255) / 256, 256>>>(cnt, N);
    k_hist<<<(E + 255) / 256, 256>>>(ei, cnt, E, N);
    k_scan1<<<nb, 512>>>(cnt, rowptr, bsum, N);
    k_scan2<<<1, 1024>>>(bsum, boff, nb);
    k_scan3<<<nb, 512>>>(rowptr, boff, cnt, N);
    k_invdeg<<<(N + 255) / 256, 256>>>(rowptr, inv, degc, N);
    k_fill<<<(E + 255) / 256, 256>>>(ei, rowptr, cnt, csr_src, csr_eid, E, N);

    // weight precompute
    k_precompute<<<2, 128>>>(We1, be1, Wl1, bl1, br1, We2, be2, Wl2, bl2, br2, P, bv1, bv0);

    // ---- layer 1 ----
    k_agg_l1<<<agrid, 256>>>(x, ea, rowptr, csr_src, csr_eid, xsum, eagg, N);
    k_gemm_sage_tc<<<ggrid, 256>>>(xsum, eagg, x, Wl1, P, Wr1,
                                   bv0, bv1, inv, degc, h1, N, 1);

    // ---- layer 2 ----
    k_agg_l2<<<agrid, 256>>>(h1, rowptr, csr_src, xsum, N);
    k_gemm_sage_tc<<<ggrid, 256>>>(xsum, eagg, h1, Wl2, P + 4096, Wr2,
                                   bv0 + 128, bv1 + 128, inv, degc, h2, N, 1);

    // ---- edge predictor (factored) ----
    k_gemm_sage_tc<<<ggrid, 256>>>(h2, nullptr, nullptr, Wp1, nullptr, nullptr,
                                   bp1, nullptr, nullptr, nullptr, xsum, N, 0);
    k_gemm_sage_tc<<<ggrid, 256>>>(h2, nullptr, nullptr, Wp1 + 128 * 128, nullptr, nullptr,
                                   nullptr, nullptr, nullptr, nullptr, h1, N, 0);

    k_edge_final<<<egrid, 256>>>(xsum, h1, ei, Wp2, bp2, out, E, N);
}

// round 9
// speedup vs baseline: 1.2698x; 1.2698x over previous
#include <cuda_runtime.h>
#include <cstdint>

#define N_NODES_MAX 100000
#define N_EDGES_MAX 600000

// Scratch (device globals)
__device__ __align__(16) float g_xsum[(size_t)N_NODES_MAX * 128];  // mean-agg; reused as 'a'
__device__ __align__(16) float g_h1  [(size_t)N_NODES_MAX * 128];  // layer-1 out; reused as 'b'
__device__ __align__(16) float g_h2  [(size_t)N_NODES_MAX * 128];  // layer-2 out
__device__ __align__(16) float g_eagg[(size_t)N_NODES_MAX * 32];   // mean edge_attr per dst
__device__ __align__(16) float g_degc[N_NODES_MAX];                // deg>0 ? 1 : 0
__device__ __align__(16) float g_P   [2 * 32 * 128];               // We_l @ Wl_l
__device__ __align__(16) float g_bv1 [2 * 128];                    // be_l @ Wl_l
__device__ __align__(16) float g_bv0 [2 * 128];                    // bl_l + br_l
// CSR (built per launch)
__device__ int g_rowptr[N_NODES_MAX + 1];
__device__ int g_cnt   [N_NODES_MAX];
__device__ int g_bsum  [1024];
__device__ int g_boff  [1024];
__device__ int g_csr_src[N_EDGES_MAX];
__device__ int g_csr_eid[N_EDGES_MAX];

// ---------------------------------------------------------------------------
// helpers
// ---------------------------------------------------------------------------
__device__ __forceinline__ uint32_t to_tf32(float v) {
    uint32_t u;
    asm("cvt.rna.tf32.f32 %0, %1;" : "=r"(u) : "f"(v));
    return u;
}
__device__ __forceinline__ void mma_tf32(float c[4], const uint32_t a[4],
                                         uint32_t b0, uint32_t b1) {
    asm("mma.sync.aligned.m16n8k8.row.col.f32.tf32.tf32.f32 "
        "{%0,%1,%2,%3}, {%4,%5,%6,%7}, {%8,%9}, {%0,%1,%2,%3};"
        : "+f"(c[0]), "+f"(c[1]), "+f"(c[2]), "+f"(c[3])
        : "r"(a[0]), "r"(a[1]), "r"(a[2]), "r"(a[3]), "r"(b0), "r"(b1));
}
__device__ __forceinline__ void cp16(uint32_t dst, const void* src, int srcsize) {
    asm volatile("cp.async.ca.shared.global [%0], [%1], 16, %2;"
                 :: "r"(dst), "l"(src), "r"(srcsize) : "memory");
}
__device__ __forceinline__ void cp_commit() {
    asm volatile("cp.async.commit_group;" ::: "memory");
}
template <int N>
__device__ __forceinline__ void cp_wait() {
    asm volatile("cp.async.wait_group %0;" :: "n"(N) : "memory");
}

// ---------------------------------------------------------------------------
// CSR build
// ---------------------------------------------------------------------------
__global__ void k_zero_int(int* __restrict__ p, int n) {
    int i = blockIdx.x * blockDim.x + threadIdx.x;
    if (i < n) p[i] = 0;
}

__global__ void k_hist(const int* __restrict__ ei, int* __restrict__ cnt, int E, int N) {
    int e = blockIdx.x * blockDim.x + threadIdx.x;
    if (e < E) {
        int d = ei[E + e];
        if ((unsigned)d < (unsigned)N) atomicAdd(&cnt[d], 1);
    }
}

__global__ void k_scan1(const int* __restrict__ cnt, int* __restrict__ rowptr,
                        int* __restrict__ bsum, int N) {
    __shared__ int sm[512];
    int t = threadIdx.x, b = blockIdx.x, i = b * 512 + t;
    int v = (i < N) ? cnt[i] : 0;
    sm[t] = v;
    __syncthreads();
    #pragma unroll
    for (int off = 1; off < 512; off <<= 1) {
        int add = (t >= off) ? sm[t - off] : 0;
        __syncthreads();
        sm[t] += add;
        __syncthreads();
    }
    if (i < N) rowptr[i + 1] = sm[t];
    if (t == 511) bsum[b] = sm[511];
}

__global__ void k_scan2(const int* __restrict__ bsum, int* __restrict__ boff, int nb) {
    __shared__ int sm[1024];
    int t = threadIdx.x;
    sm[t] = (t < nb) ? bsum[t] : 0;
    __syncthreads();
    #pragma unroll
    for (int off = 1; off < 1024; off <<= 1) {
        int add = (t >= off) ? sm[t - off] : 0;
        __syncthreads();
        sm[t] += add;
        __syncthreads();
    }
    if (t < nb) boff[t] = (t == 0) ? 0 : sm[t - 1];
}

// add block offsets; degc from cnt; zero cnt (reused as fill cursor)
__global__ void k_scan3(int* __restrict__ rowptr, const int* __restrict__ boff,
                        int* __restrict__ cnt, float* __restrict__ degc, int N) {
    int t = threadIdx.x, b = blockIdx.x, i = b * 512 + t;
    if (i < N) {
        rowptr[i + 1] += boff[b];
        degc[i] = cnt[i] > 0 ? 1.f : 0.f;
        cnt[i] = 0;
        if (i == 0) rowptr[0] = 0;
    }
}

__global__ void k_fill(const int* __restrict__ ei, const int* __restrict__ rowptr,
                       int* __restrict__ cnt, int* __restrict__ csr_src,
                       int* __restrict__ csr_eid, int E, int N) {
    int e = blockIdx.x * blockDim.x + threadIdx.x;
    if (e < E) {
        int s = ei[e];
        int d = ei[E + e];
        if ((unsigned)d < (unsigned)N) {
            int pos = rowptr[d] + atomicAdd(&cnt[d], 1);
            csr_src[pos] = s;
            csr_eid[pos] = e;
        }
    }
}

// ---------------------------------------------------------------------------
// CSR aggregation: one warp per node, register accumulate, MEAN written.
// Layer 1 also computes mean edge_attr (eagg).
// ---------------------------------------------------------------------------
__global__ void k_agg_l1(const float* __restrict__ x, const float* __restrict__ ea,
                         const int* __restrict__ rowptr,
                         const int* __restrict__ csr_src, const int* __restrict__ csr_eid,
                         float* __restrict__ xsum, float* __restrict__ eagg, int N) {
    int lane = threadIdx.x & 31;
    int n = (blockIdx.x * blockDim.x + threadIdx.x) >> 5;
    if (n >= N) return;
    int beg = rowptr[n], end = rowptr[n + 1];
    float inv = 1.f / fmaxf((float)(end - beg), 1.f);
    const float4* x4 = (const float4*)x;
    float4 acc = make_float4(0.f, 0.f, 0.f, 0.f);
    float eacc = 0.f;
    int i = beg;
    for (; i + 1 < end; i += 2) {
        int s0 = __ldg(&csr_src[i]),     e0 = __ldg(&csr_eid[i]);
        int s1 = __ldg(&csr_src[i + 1]), e1 = __ldg(&csr_eid[i + 1]);
        float4 v0 = __ldg(x4 + (size_t)s0 * 32 + lane);
        float4 v1 = __ldg(x4 + (size_t)s1 * 32 + lane);
        float w0 = __ldg(&ea[(size_t)e0 * 32 + lane]);
        float w1 = __ldg(&ea[(size_t)e1 * 32 + lane]);
        acc.x += v0.x + v1.x; acc.y += v0.y + v1.y;
        acc.z += v0.z + v1.z; acc.w += v0.w + v1.w;
        eacc += w0 + w1;
    }
    if (i < end) {
        int s0 = __ldg(&csr_src[i]), e0 = __ldg(&csr_eid[i]);
        float4 v0 = __ldg(x4 + (size_t)s0 * 32 + lane);
        float w0 = __ldg(&ea[(size_t)e0 * 32 + lane]);
        acc.x += v0.x; acc.y += v0.y; acc.z += v0.z; acc.w += v0.w;
        eacc += w0;
    }
    acc.x *= inv; acc.y *= inv; acc.z *= inv; acc.w *= inv;
    ((float4*)xsum)[(size_t)n * 32 + lane] = acc;
    eagg[(size_t)n * 32 + lane] = eacc * inv;
}

__global__ void k_agg_l2(const float* __restrict__ x,
                         const int* __restrict__ rowptr,
                         const int* __restrict__ csr_src,
                         float* __restrict__ xsum, int N) {
    int lane = threadIdx.x & 31;
    int n = (blockIdx.x * blockDim.x + threadIdx.x) >> 5;
    if (n >= N) return;
    int beg = rowptr[n], end = rowptr[n + 1];
    float inv = 1.f / fmaxf((float)(end - beg), 1.f);
    const float4* x4 = (const float4*)x;
    float4 acc = make_float4(0.f, 0.f, 0.f, 0.f);
    int i = beg;
    for (; i + 1 < end; i += 2) {
        int s0 = __ldg(&csr_src[i]);
        int s1 = __ldg(&csr_src[i + 1]);
        float4 v0 = __ldg(x4 + (size_t)s0 * 32 + lane);
        float4 v1 = __ldg(x4 + (size_t)s1 * 32 + lane);
        acc.x += v0.x + v1.x; acc.y += v0.y + v1.y;
        acc.z += v0.z + v1.z; acc.w += v0.w + v1.w;
    }
    if (i < end) {
        int s0 = __ldg(&csr_src[i]);
        float4 v0 = __ldg(x4 + (size_t)s0 * 32 + lane);
        acc.x += v0.x; acc.y += v0.y; acc.z += v0.z; acc.w += v0.w;
    }
    acc.x *= inv; acc.y *= inv; acc.z *= inv; acc.w *= inv;
    ((float4*)xsum)[(size_t)n * 32 + lane] = acc;
}

// ---------------------------------------------------------------------------
// Precompute P_l = We_l @ Wl_l, bv1_l = be_l @ Wl_l, bv0_l = bl_l + br_l.
// ---------------------------------------------------------------------------
__global__ void k_precompute(const float* We1, const float* be1, const float* Wl1,
                             const float* bl1, const float* br1,
                             const float* We2, const float* be2, const float* Wl2,
                             const float* bl2, const float* br2,
                             float* P, float* bv1, float* bv0) {
    int l = blockIdx.x;
    int j = threadIdx.x;
    const float* We = l ? We2 : We1;
    const float* be = l ? be2 : be1;
    const float* Wl = l ? Wl2 : Wl1;
    const float* bl = l ? bl2 : bl1;
    const float* br = l ? br2 : br1;

    for (int i = 0; i < 32; i++) {
        float acc = 0.f;
        for (int k = 0; k < 128; k++) acc = fmaf(We[i * 128 + k], Wl[k * 128 + j], acc);
        P[l * 4096 + i * 128 + j] = acc;
    }
    float a1 = 0.f;
    for (int k = 0; k < 128; k++) a1 = fmaf(be[k], Wl[k * 128 + j], a1);
    bv1[l * 128 + j] = a1;
    bv0[l * 128 + j] = bl[j] + br[j];
}

// ---------------------------------------------------------------------------
// Tensor-core SAGE node GEMM (tf32 mma.sync m16n8k8), cp.async double-buffered:
//   C = act( A1 @ W1 + (A2 @ P)? + (B @ W2)? + bv0? + degc[m]*bv1? )
// (mean scaling pre-folded into A1/A2 by aggregation kernels.)
// BM=128, BN=128, BK=16. 256 threads = 8 warps 4x2; warp = 32x64.
// A smem [m][k] stride 20  -> a-frag banks (20g+q)%32 all distinct.
// W smem [k][j] stride 128, XOR swizzle j^=(k&3)<<3 -> b-frag banks 8(nt^q)+g.
// Both tiles loaded with 16B cp.async (2 per thread per tile).
// ---------------------------------------------------------------------------
__global__ __launch_bounds__(256, 2)
void k_gemm_sage_tc(const float* __restrict__ A1,
                    const float* __restrict__ A2,
                    const float* __restrict__ B,
                    const float* __restrict__ W1,
                    const float* __restrict__ P,
                    const float* __restrict__ W2,
                    const float* __restrict__ bv0,
                    const float* __restrict__ bv1,
                    const float* __restrict__ degc,
                    float* __restrict__ C,
                    int M, int relu) {
    __shared__ __align__(16) float As[2][128][20];
    __shared__ __align__(16) float Ws[2][16][128];

    const int tid    = threadIdx.x;
    const int lane   = tid & 31;
    const int warp   = tid >> 5;
    const int gid    = lane >> 2;
    const int qid    = lane & 3;
    const int warp_m = warp >> 1;
    const int warp_n = warp & 1;
    const int m0     = blockIdx.x * 128;

    // per-thread load coordinates (2 x 16B per tile for each of A, W)
    const int am0  = (tid * 2) >> 3;            // lin=tid*2+i -> m = lin>>2
    const int asub = (tid * 2) & 3;             // k-quad within row (i toggles bit0 of lin)
    // A: lin i=0 -> (m=am0, sub=asub); i=1 -> lin+1
    const int wk0  = (tid * 2) >> 5;            // k = lin>>5 (same for i=0,1 since tid*2 even)
    // W: jj quads

    float c[2][8][4];
    #pragma unroll
    for (int mt = 0; mt < 2; mt++)
        #pragma unroll
        for (int nt = 0; nt < 8; nt++)
            #pragma unroll
            for (int i = 0; i < 4; i++) c[mt][nt][i] = 0.f;

    const int ktiles = (A2 != nullptr) ? 18 : 8;

    auto issue_tile = [&](int kt, int buf) {
        const float* Ain;
        const float* Win;
        int kb, astride;
        if (kt < 8)       { Ain = A1; Win = W1; kb = kt * 16;        astride = 128; }
        else if (kt < 10) { Ain = A2; Win = P;  kb = (kt - 8) * 16;  astride = 32;  }
        else              { Ain = B;  Win = W2; kb = (kt - 10) * 16; astride = 128; }
        // A: 512 float4 -> 2 per thread
        #pragma unroll
        for (int i = 0; i < 2; i++) {
            int lin = tid * 2 + i;              // 0..511
            int m = lin >> 2;
            int sub = (lin & 3) * 4;
            int gm = m0 + m;
            uint32_t dst = (uint32_t)__cvta_generic_to_shared(&As[buf][m][sub]);
            const float* src = Ain + (size_t)gm * astride + kb + sub;
            cp16(dst, src, gm < M ? 16 : 0);
        }
        // W: 512 float4 -> 2 per thread (XOR swizzle)
        #pragma unroll
        for (int i = 0; i < 2; i++) {
            int lin = tid * 2 + i;
            int k = lin >> 5;
            int jj = (lin & 31) * 4;
            int jsw = jj ^ ((k & 3) << 3);
            uint32_t dst = (uint32_t)__cvta_generic_to_shared(&Ws[buf][k][jsw]);
            const float* src = Win + (size_t)(kb + k) * 128 + jj;
            cp16(dst, src, 16);
        }
        cp_commit();
    };

    issue_tile(0, 0);
    int buf = 0;

    for (int kt = 0; kt < ktiles; kt++) {
        const bool has_next = (kt + 1 < ktiles);
        if (has_next) issue_tile(kt + 1, buf ^ 1);
        if (has_next) cp_wait<1>(); else cp_wait<0>();
        __syncthreads();

        #pragma unroll
        for (int ks = 0; ks < 2; ks++) {
            const int k8 = ks * 8;
            uint32_t a[2][4];
            #pragma unroll
            for (int mt = 0; mt < 2; mt++) {
                int row = warp_m * 32 + mt * 16 + gid;
                a[mt][0] = to_tf32(As[buf][row][k8 + qid]);
                a[mt][1] = to_tf32(As[buf][row + 8][k8 + qid]);
                a[mt][2] = to_tf32(As[buf][row][k8 + qid + 4]);
                a[mt][3] = to_tf32(As[buf][row + 8][k8 + qid + 4]);
            }
            #pragma unroll
            for (int nt = 0; nt < 8; nt++) {
                int col = warp_n * 64 + nt * 8 + gid;
                int csw = col ^ (qid << 3);
                uint32_t b0 = to_tf32(Ws[buf][k8 + qid][csw]);
                uint32_t b1 = to_tf32(Ws[buf][k8 + qid + 4][csw]);
                mma_tf32(c[0][nt], a[0], b0, b1);
                mma_tf32(c[1][nt], a[1], b0, b1);
            }
        }
        __syncthreads();     // protect buf from next issue
        buf ^= 1;
    }

    #pragma unroll
    for (int mt = 0; mt < 2; mt++) {
        int rbase = m0 + warp_m * 32 + mt * 16 + gid;
        #pragma unroll
        for (int h = 0; h < 2; h++) {
            int r = rbase + h * 8;
            if (r >= M) continue;
            float coef = (bv1 && degc) ? degc[r] : 0.f;
            #pragma unroll
            for (int nt = 0; nt < 8; nt++) {
                int j = warp_n * 64 + nt * 8 + qid * 2;
                float v0 = c[mt][nt][h * 2 + 0];
                float v1 = c[mt][nt][h * 2 + 1];
                if (bv0) { v0 += bv0[j]; v1 += bv0[j + 1]; }
                if (bv1) { v0 += coef * bv1[j]; v1 += coef * bv1[j + 1]; }
                if (relu) { v0 = fmaxf(v0, 0.f); v1 = fmaxf(v1, 0.f); }
                *(float2*)&C[(size_t)r * 128 + j] = make_float2(v0, v1);
            }
        }
    }
}

// ---------------------------------------------------------------------------
// Final edge predictor: out[e] = relu(a[src] + b[dst]) @ Wp2 + bp2
// ---------------------------------------------------------------------------
__global__ void k_edge_final(const float* __restrict__ a,
                             const float* __restrict__ b,
                             const int* __restrict__ ei,
                             const float* __restrict__ Wp2,
                             const float* __restrict__ bp2,
                             float* __restrict__ out,
                             int E, int N) {
    int lane = threadIdx.x & 31;
    int warp = (blockIdx.x * blockDim.x + threadIdx.x) >> 5;
    int nwarp = (gridDim.x * blockDim.x) >> 5;

    float4 w01 = ((const float4*)Wp2)[lane * 2];
    float4 w23 = ((const float4*)Wp2)[lane * 2 + 1];
    float b0 = bp2[0], b1 = bp2[1];

    for (int e = warp; e < E; e += nwarp) {
        int s = ei[e];
        int d = ei[E + e];
        if ((unsigned)s >= (unsigned)N || (unsigned)d >= (unsigned)N) continue;
        float4 av = __ldg((const float4*)a + (size_t)s * 32 + lane);
        float4 bv = __ldg((const float4*)b + (size_t)d * 32 + lane);
        float z0 = fmaxf(av.x + bv.x, 0.f);
        float z1 = fmaxf(av.y + bv.y, 0.f);
        float z2 = fmaxf(av.z + bv.z, 0.f);
        float z3 = fmaxf(av.w + bv.w, 0.f);
        float o0 = z0 * w01.x + z1 * w01.z + z2 * w23.x + z3 * w23.z;
        float o1 = z0 * w01.y + z1 * w01.w + z2 * w23.y + z3 * w23.w;
        #pragma unroll
        for (int off = 16; off > 0; off >>= 1) {
            o0 += __shfl_xor_sync(0xffffffffu, o0, off);
            o1 += __shfl_xor_sync(0xffffffffu, o1, off);
        }
        if (lane == 0) {
            float2 r = make_float2(o0 + b0, o1 + b1);
            *(float2*)&out[(size_t)e * 2] = r;
        }
    }
}

// ---------------------------------------------------------------------------
extern "C" void kernel_launch(void* const* d_in, const int* in_sizes, int n_in,
                              void* d_out, int out_size) {
    const float* x    = (const float*)d_in[0];
    const int*   ei   = (const int*)d_in[1];     // int32
    const float* ea   = (const float*)d_in[2];
    const float* We1  = (const float*)d_in[3];
    const float* be1  = (const float*)d_in[4];
    const float* Wl1  = (const float*)d_in[5];
    const float* bl1  = (const float*)d_in[6];
    const float* Wr1  = (const float*)d_in[7];
    const float* br1  = (const float*)d_in[8];
    const float* We2  = (const float*)d_in[9];
    const float* be2  = (const float*)d_in[10];
    const float* Wl2  = (const float*)d_in[11];
    const float* bl2  = (const float*)d_in[12];
    const float* Wr2  = (const float*)d_in[13];
    const float* br2  = (const float*)d_in[14];
    const float* Wp1  = (const float*)d_in[15];
    const float* bp1  = (const float*)d_in[16];
    const float* Wp2  = (const float*)d_in[17];
    const float* bp2  = (const float*)d_in[18];
    float*       out  = (float*)d_out;

    const int N = in_sizes[0] / 128;
    const int E = in_sizes[2] / 32;

    float *xsum, *h1, *h2, *eagg, *degc, *P, *bv1, *bv0;
    int *rowptr, *cnt, *bsum, *boff, *csr_src, *csr_eid;
    cudaGetSymbolAddress((void**)&xsum, g_xsum);
    cudaGetSymbolAddress((void**)&h1,   g_h1);
    cudaGetSymbolAddress((void**)&h2,   g_h2);
    cudaGetSymbolAddress((void**)&eagg, g_eagg);
    cudaGetSymbolAddress((void**)&degc, g_degc);
    cudaGetSymbolAddress((void**)&P,    g_P);
    cudaGetSymbolAddress((void**)&bv1,  g_bv1);
    cudaGetSymbolAddress((void**)&bv0,  g_bv0);
    cudaGetSymbolAddress((void**)&rowptr, g_rowptr);
    cudaGetSymbolAddress((void**)&cnt,    g_cnt);
    cudaGetSymbolAddress((void**)&bsum,   g_bsum);
    cudaGetSymbolAddress((void**)&boff,   g_boff);
    cudaGetSymbolAddress((void**)&csr_src, g_csr_src);
    cudaGetSymbolAddress((void**)&csr_eid, g_csr_eid);

    const int nb    = (N + 511) / 512;
    const int ggrid = (N + 127) / 128;
    const int agrid = (N + 7) / 8;
    const int egrid = 2368;

    // ---- CSR build ----
    k_zero_int<<<(N + 255) / 256, 256>>>(cnt, N);
    k_hist<<<(E + 255) / 256, 256>>>(ei, cnt, E, N);
    k_scan1<<<nb, 512>>>(cnt, rowptr, bsum, N);
    k_scan2<<<1, 1024>>>(bsum, boff, nb);
    k_scan3<<<nb, 512>>>(rowptr, boff, cnt, degc, N);
    k_fill<<<(E + 255) / 256, 256>>>(ei, rowptr, cnt, csr_src, csr_eid, E, N);

    // weight precompute
    k_precompute<<<2, 128>>>(We1, be1, Wl1, bl1, br1, We2, be2, Wl2, bl2, br2, P, bv1, bv0);

    // ---- layer 1 ----
    k_agg_l1<<<agrid, 256>>>(x, ea, rowptr, csr_src, csr_eid, xsum, eagg, N);
    k_gemm_sage_tc<<<ggrid, 256>>>(xsum, eagg, x, Wl1, P, Wr1,
                                   bv0, bv1, degc, h1, N, 1);

    // ---- layer 2 ----
    k_agg_l2<<<agrid, 256>>>(h1, rowptr, csr_src, xsum, N);
    k_gemm_sage_tc<<<ggrid, 256>>>(xsum, eagg, h1, Wl2, P + 4096, Wr2,
                                   bv0 + 128, bv1 + 128, degc, h2, N, 1);

    // ---- edge predictor (factored) ----
    k_gemm_sage_tc<<<ggrid, 256>>>(h2, nullptr, nullptr, Wp1, nullptr, nullptr,
                                   bp1, nullptr, nullptr, xsum, N, 0);
    k_gemm_sage_tc<<<ggrid, 256>>>(h2, nullptr, nullptr, Wp1 + 128 * 128, nullptr, nullptr,
                                   nullptr, nullptr, nullptr, h1, N, 0);

    k_edge_final<<<egrid, 256>>>(xsum, h1, ei, Wp2, bp2, out, E, N);
}

// round 12
// speedup vs baseline: 1.3443x; 1.0587x over previous
#include <cuda_runtime.h>
#include <cuda_fp16.h>
#include <cstdint>

#define N_NODES_MAX 100000
#define N_EDGES_MAX 600000

// ---------------------------------------------------------------------------
// Scratch (device globals)
// ---------------------------------------------------------------------------
__device__ __align__(16) __half g_aggh [(size_t)N_NODES_MAX * 128];  // mean agg (half)
__device__ __align__(16) __half g_eaggh[(size_t)N_NODES_MAX * 32];   // mean edge_attr (half)
__device__ __align__(16) __half g_xh   [(size_t)N_NODES_MAX * 128];  // half(x)
__device__ __align__(16) __half g_h1h  [(size_t)N_NODES_MAX * 128];  // layer-1 out (half)
__device__ __align__(16) __half g_h2h  [(size_t)N_NODES_MAX * 128];  // layer-2 out (half)
__device__ __align__(16) float  g_af   [(size_t)N_NODES_MAX * 128];  // predictor 'a' (fp32)
__device__ __align__(16) float  g_bf   [(size_t)N_NODES_MAX * 128];  // predictor 'b' (fp32)
__device__ __align__(16) float  g_degc [N_NODES_MAX];                // deg>0 ? 1 : 0
__device__ __align__(16) __half g_Wcath[2 * 128 * 288];              // [n][Wl^T|P^T|Wr^T]
__device__ __align__(16) __half g_Wpth [2 * 128 * 128];              // Wp1a^T, Wp1b^T
__device__ __align__(16) float  g_bv1  [2 * 128];                    // be_l @ Wl_l
__device__ __align__(16) float  g_bv0  [2 * 128];                    // bl_l + br_l
// CSR
__device__ int g_rowptr[N_NODES_MAX + 1];
__device__ int g_cnt   [N_NODES_MAX];
__device__ int g_bsum  [1024];
__device__ int g_boff  [1024];
__device__ int g_csr_src[N_EDGES_MAX];
__device__ int g_csr_eid[N_EDGES_MAX];

// ---------------------------------------------------------------------------
// helpers
// ---------------------------------------------------------------------------
__device__ __forceinline__ void cp16(uint32_t dst, const void* src, int srcsize) {
    asm volatile("cp.async.ca.shared.global [%0], [%1], 16, %2;"
                 :: "r"(dst), "l"(src), "r"(srcsize) : "memory");
}
__device__ __forceinline__ void cp_commit() {
    asm volatile("cp.async.commit_group;" ::: "memory");
}
template <int N>
__device__ __forceinline__ void cp_wait() {
    asm volatile("cp.async.wait_group %0;" :: "n"(N) : "memory");
}
__device__ __forceinline__ void mma_f16(float c[4], const uint32_t a[4],
                                        uint32_t b0, uint32_t b1) {
    asm("mma.sync.aligned.m16n8k16.row.col.f32.f16.f16.f32 "
        "{%0,%1,%2,%3}, {%4,%5,%6,%7}, {%8,%9}, {%0,%1,%2,%3};"
        : "+f"(c[0]), "+f"(c[1]), "+f"(c[2]), "+f"(c[3])
        : "r"(a[0]), "r"(a[1]), "r"(a[2]), "r"(a[3]), "r"(b0), "r"(b1));
}

// ---------------------------------------------------------------------------
// CSR build
// ---------------------------------------------------------------------------
__global__ void k_zero_int(int* __restrict__ p, int n) {
    int i = blockIdx.x * blockDim.x + threadIdx.x;
    if (i < n) p[i] = 0;
}
__global__ void k_hist(const int* __restrict__ ei, int* __restrict__ cnt, int E, int N) {
    int e = blockIdx.x * blockDim.x + threadIdx.x;
    if (e < E) {
        int d = ei[E + e];
        if ((unsigned)d < (unsigned)N) atomicAdd(&cnt[d], 1);
    }
}
__global__ void k_scan1(const int* __restrict__ cnt, int* __restrict__ rowptr,
                        int* __restrict__ bsum, int N) {
    __shared__ int sm[512];
    int t = threadIdx.x, b = blockIdx.x, i = b * 512 + t;
    int v = (i < N) ? cnt[i] : 0;
    sm[t] = v;
    __syncthreads();
    #pragma unroll
    for (int off = 1; off < 512; off <<= 1) {
        int add = (t >= off) ? sm[t - off] : 0;
        __syncthreads();
        sm[t] += add;
        __syncthreads();
    }
    if (i < N) rowptr[i + 1] = sm[t];
    if (t == 511) bsum[b] = sm[511];
}
__global__ void k_scan2(const int* __restrict__ bsum, int* __restrict__ boff, int nb) {
    __shared__ int sm[1024];
    int t = threadIdx.x;
    sm[t] = (t < nb) ? bsum[t] : 0;
    __syncthreads();
    #pragma unroll
    for (int off = 1; off < 1024; off <<= 1) {
        int add = (t >= off) ? sm[t - off] : 0;
        __syncthreads();
        sm[t] += add;
        __syncthreads();
    }
    if (t < nb) boff[t] = (t == 0) ? 0 : sm[t - 1];
}
__global__ void k_scan3(int* __restrict__ rowptr, const int* __restrict__ boff,
                        int* __restrict__ cnt, float* __restrict__ degc, int N) {
    int t = threadIdx.x, b = blockIdx.x, i = b * 512 + t;
    if (i < N) {
        rowptr[i + 1] += boff[b];
        degc[i] = cnt[i] > 0 ? 1.f : 0.f;
        cnt[i] = 0;
        if (i == 0) rowptr[0] = 0;
    }
}
__global__ void k_fill(const int* __restrict__ ei, const int* __restrict__ rowptr,
                       int* __restrict__ cnt, int* __restrict__ csr_src,
                       int* __restrict__ csr_eid, int E, int N) {
    int e = blockIdx.x * blockDim.x + threadIdx.x;
    if (e < E) {
        int s = ei[e];
        int d = ei[E + e];
        if ((unsigned)d < (unsigned)N) {
            int pos = rowptr[d] + atomicAdd(&cnt[d], 1);
            csr_src[pos] = s;
            csr_eid[pos] = e;
        }
    }
}

// ---------------------------------------------------------------------------
// x -> half copy
// ---------------------------------------------------------------------------
__global__ void k_xhalf(const float4* __restrict__ x, uint2* __restrict__ xh, int n4) {
    int i = blockIdx.x * blockDim.x + threadIdx.x;
    int stride = gridDim.x * blockDim.x;
    for (; i < n4; i += stride) {
        float4 v = x[i];
        __half2 p0 = __floats2half2_rn(v.x, v.y);
        __half2 p1 = __floats2half2_rn(v.z, v.w);
        uint2 u;
        u.x = *(uint32_t*)&p0;
        u.y = *(uint32_t*)&p1;
        xh[i] = u;
    }
}

// ---------------------------------------------------------------------------
// CSR aggregation: one warp per node, fp32 accumulate, MEAN written as half.
// ---------------------------------------------------------------------------
__global__ void k_agg_l1(const float* __restrict__ x, const float* __restrict__ ea,
                         const int* __restrict__ rowptr,
                         const int* __restrict__ csr_src, const int* __restrict__ csr_eid,
                         __half* __restrict__ aggh, __half* __restrict__ eaggh, int N) {
    int lane = threadIdx.x & 31;
    int n = (blockIdx.x * blockDim.x + threadIdx.x) >> 5;
    if (n >= N) return;
    int beg = rowptr[n], end = rowptr[n + 1];
    float inv = 1.f / fmaxf((float)(end - beg), 1.f);
    const float4* x4 = (const float4*)x;
    float4 acc = make_float4(0.f, 0.f, 0.f, 0.f);
    float eacc = 0.f;
    int i = beg;
    for (; i + 1 < end; i += 2) {
        int s0 = __ldg(&csr_src[i]),     e0 = __ldg(&csr_eid[i]);
        int s1 = __ldg(&csr_src[i + 1]), e1 = __ldg(&csr_eid[i + 1]);
        float4 v0 = __ldg(x4 + (size_t)s0 * 32 + lane);
        float4 v1 = __ldg(x4 + (size_t)s1 * 32 + lane);
        float w0 = __ldg(&ea[(size_t)e0 * 32 + lane]);
        float w1 = __ldg(&ea[(size_t)e1 * 32 + lane]);
        acc.x += v0.x + v1.x; acc.y += v0.y + v1.y;
        acc.z += v0.z + v1.z; acc.w += v0.w + v1.w;
        eacc += w0 + w1;
    }
    if (i < end) {
        int s0 = __ldg(&csr_src[i]), e0 = __ldg(&csr_eid[i]);
        float4 v0 = __ldg(x4 + (size_t)s0 * 32 + lane);
        float w0 = __ldg(&ea[(size_t)e0 * 32 + lane]);
        acc.x += v0.x; acc.y += v0.y; acc.z += v0.z; acc.w += v0.w;
        eacc += w0;
    }
    __half2 p0 = __floats2half2_rn(acc.x * inv, acc.y * inv);
    __half2 p1 = __floats2half2_rn(acc.z * inv, acc.w * inv);
    uint2 u;
    u.x = *(uint32_t*)&p0;
    u.y = *(uint32_t*)&p1;
    ((uint2*)aggh)[(size_t)n * 32 + lane] = u;
    eaggh[(size_t)n * 32 + lane] = __float2half_rn(eacc * inv);
}

__global__ void k_agg_l2(const __half* __restrict__ xh,
                         const int* __restrict__ rowptr,
                         const int* __restrict__ csr_src,
                         __half* __restrict__ aggh, int N) {
    int lane = threadIdx.x & 31;
    int n = (blockIdx.x * blockDim.x + threadIdx.x) >> 5;
    if (n >= N) return;
    int beg = rowptr[n], end = rowptr[n + 1];
    float inv = 1.f / fmaxf((float)(end - beg), 1.f);
    const uint2* x2 = (const uint2*)xh;
    float4 acc = make_float4(0.f, 0.f, 0.f, 0.f);
    for (int i = beg; i < end; i++) {
        int s0 = __ldg(&csr_src[i]);
        uint2 u = __ldg(x2 + (size_t)s0 * 32 + lane);
        float2 f0 = __half22float2(*(__half2*)&u.x);
        float2 f1 = __half22float2(*(__half2*)&u.y);
        acc.x += f0.x; acc.y += f0.y; acc.z += f1.x; acc.w += f1.y;
    }
    __half2 p0 = __floats2half2_rn(acc.x * inv, acc.y * inv);
    __half2 p1 = __floats2half2_rn(acc.z * inv, acc.w * inv);
    uint2 u;
    u.x = *(uint32_t*)&p0;
    u.y = *(uint32_t*)&p1;
    ((uint2*)aggh)[(size_t)n * 32 + lane] = u;
}

// ---------------------------------------------------------------------------
// Weight prep (half, transposed K-major):
// block 0/1: Wcat[l][n][0:128]=Wl^T, [128:160]=(We@Wl)^T, [160:288]=Wr^T;
//            bv1 = be@Wl, bv0 = bl+br.
// block 2:   Wpt[0]=Wp1[:128]^T, Wpt[1]=Wp1[128:]^T.
// ---------------------------------------------------------------------------
__global__ void k_wprep(const float* We1, const float* be1, const float* Wl1,
                        const float* bl1, const float* br1, const float* Wr1,
                        const float* We2, const float* be2, const float* Wl2,
                        const float* bl2, const float* br2, const float* Wr2,
                        const float* Wp1,
                        __half* Wcat, __half* Wpt, float* bv1, float* bv0) {
    int l = blockIdx.x;
    int j = threadIdx.x;
    if (l < 2) {
        const float* We = l ? We2 : We1;
        const float* be = l ? be2 : be1;
        const float* Wl = l ? Wl2 : Wl1;
        const float* bl = l ? bl2 : bl1;
        const float* br = l ? br2 : br1;
        const float* Wr = l ? Wr2 : Wr1;
        __half* row = Wcat + (size_t)l * 128 * 288 + (size_t)j * 288;
        for (int k = 0; k < 128; k++) row[k] = __float2half_rn(Wl[k * 128 + j]);
        for (int i = 0; i < 32; i++) {
            float acc = 0.f;
            for (int k = 0; k < 128; k++) acc = fmaf(We[i * 128 + k], Wl[k * 128 + j], acc);
            row[128 + i] = __float2half_rn(acc);
        }
        for (int k = 0; k < 128; k++) row[160 + k] = __float2half_rn(Wr[k * 128 + j]);
        float a1 = 0.f;
        for (int k = 0; k < 128; k++) a1 = fmaf(be[k], Wl[k * 128 + j], a1);
        bv1[l * 128 + j] = a1;
        bv0[l * 128 + j] = bl[j] + br[j];
    } else {
        __half* ra = Wpt + (size_t)j * 128;
        __half* rb = Wpt + (size_t)128 * 128 + (size_t)j * 128;
        for (int k = 0; k < 128; k++) {
            ra[k] = __float2half_rn(Wp1[k * 128 + j]);
            rb[k] = __float2half_rn(Wp1[(128 + k) * 128 + j]);
        }
    }
}

// ---------------------------------------------------------------------------
// fp16 tensor-core SAGE GEMM (mma.sync m16n8k16), cp.async double-buffered.
//   C = act( A1 @ W^T + (A2 @ P^T)? + (B @ Wr^T)? + bv0? + degc[m]*bv1? )
// BM=128, BN=128, BK=32 halves. 256 threads = 8 warps 4x2; warp = 32x64.
// smem rows padded to 20 words (40 halves): frag banks (20g+q)%32 all distinct.
//   ktiles=9: t<4 -> A1 cols t*32 | t==4 -> A2 | t>4 -> B cols (t-5)*32
//   ktiles=4: t<4 -> A1 cols t*32
// Output: half (Ch) or fp32 (Cf).
// ---------------------------------------------------------------------------
__global__ __launch_bounds__(256)
void k_gemm_f16(const __half* __restrict__ A1,
                const __half* __restrict__ A2,
                const __half* __restrict__ B,
                const __half* __restrict__ Wt, int wstride, int ktiles,
                const float* __restrict__ bv0,
                const float* __restrict__ bv1,
                const float* __restrict__ degc,
                __half* __restrict__ Ch,
                float* __restrict__ Cf,
                int M, int relu) {
    __shared__ __align__(16) uint32_t As[2][128][20];
    __shared__ __align__(16) uint32_t Bs[2][128][20];

    const int tid    = threadIdx.x;
    const int lane   = tid & 31;
    const int warp   = tid >> 5;
    const int gid    = lane >> 2;
    const int qid    = lane & 3;
    const int warp_m = warp >> 1;
    const int warp_n = warp & 1;
    const int m0     = blockIdx.x * 128;

    float c[2][8][4];
    #pragma unroll
    for (int mt = 0; mt < 2; mt++)
        #pragma unroll
        for (int nt = 0; nt < 8; nt++)
            #pragma unroll
            for (int i = 0; i < 4; i++) c[mt][nt][i] = 0.f;

    // 512 16B-chunks per tile pair (A:512, B:512) -> 2 iters x 256 threads each
    auto issue_tile = [&](int t, int buf) {
        const __half* Ap;
        int astr, akb;
        if (ktiles == 4 || t < 4) { Ap = A1; astr = 128; akb = t * 32; }
        else if (t == 4)          { Ap = A2; astr = 32;  akb = 0;      }
        else                      { Ap = B;  astr = 128; akb = (t - 5) * 32; }
        const int bkb = t * 32;
        #pragma unroll
        for (int i = 0; i < 2; i++) {
            int chunk = tid + i * 256;      // 0..511
            int r = chunk >> 2, qc = chunk & 3;
            int gm = m0 + r;
            uint32_t dst = (uint32_t)__cvta_generic_to_shared(&As[buf][r][qc * 4]);
            cp16(dst, Ap + (size_t)gm * astr + akb + qc * 8, gm < M ? 16 : 0);
        }
        #pragma unroll
        for (int i = 0; i < 2; i++) {
            int chunk = tid + i * 256;      // 0..511
            int r = chunk >> 2, qc = chunk & 3;
            uint32_t dst = (uint32_t)__cvta_generic_to_shared(&Bs[buf][r][qc * 4]);
            cp16(dst, Wt + (size_t)r * wstride + bkb + qc * 8, 16);
        }
        cp_commit();
    };

    issue_tile(0, 0);
    int buf = 0;

    for (int t = 0; t < ktiles; t++) {
        const bool has_next = (t + 1 < ktiles);
        if (has_next) issue_tile(t + 1, buf ^ 1);
        if (has_next) cp_wait<1>(); else cp_wait<0>();
        __syncthreads();

        #pragma unroll
        for (int ks = 0; ks < 2; ks++) {
            const int kw = ks * 8;          // word offset base within 20-word row
            uint32_t a[2][4];
            #pragma unroll
            for (int mt = 0; mt < 2; mt++) {
                int row = warp_m * 32 + mt * 16 + gid;
                a[mt][0] = As[buf][row][kw + qid];
                a[mt][1] = As[buf][row + 8][kw + qid];
                a[mt][2] = As[buf][row][kw + qid + 4];
                a[mt][3] = As[buf][row + 8][kw + qid + 4];
            }
            #pragma unroll
            for (int nt = 0; nt < 8; nt++) {
                int n = warp_n * 64 + nt * 8 + gid;
                uint32_t b0 = Bs[buf][n][kw + qid];
                uint32_t b1 = Bs[buf][n][kw + qid + 4];
                mma_f16(c[0][nt], a[0], b0, b1);
                mma_f16(c[1][nt], a[1], b0, b1);
            }
        }
        __syncthreads();
        buf ^= 1;
    }

    // epilogue
    #pragma unroll
    for (int mt = 0; mt < 2; mt++) {
        int rbase = m0 + warp_m * 32 + mt * 16 + gid;
        #pragma unroll
        for (int h = 0; h < 2; h++) {
            int r = rbase + h * 8;
            if (r >= M) continue;
            float coef = (bv1 && degc) ? degc[r] : 0.f;
            #pragma unroll
            for (int nt = 0; nt < 8; nt++) {
                int j = warp_n * 64 + nt * 8 + qid * 2;
                float v0 = c[mt][nt][h * 2 + 0];
                float v1 = c[mt][nt][h * 2 + 1];
                if (bv0) { v0 += bv0[j]; v1 += bv0[j + 1]; }
                if (bv1) { v0 += coef * bv1[j]; v1 += coef * bv1[j + 1]; }
                if (relu) { v0 = fmaxf(v0, 0.f); v1 = fmaxf(v1, 0.f); }
                if (Ch) {
                    __half2 p = __floats2half2_rn(v0, v1);
                    *(__half2*)&Ch[(size_t)r * 128 + j] = p;
                } else {
                    *(float2*)&Cf[(size_t)r * 128 + j] = make_float2(v0, v1);
                }
            }
        }
    }
}

// ---------------------------------------------------------------------------
// Final edge predictor: out[e] = relu(a[src] + b[dst]) @ Wp2 + bp2
// ---------------------------------------------------------------------------
__global__ void k_edge_final(const float* __restrict__ a,
                             const float* __restrict__ b,
                             const int* __restrict__ ei,
                             const float* __restrict__ Wp2,
                             const float* __restrict__ bp2,
                             float* __restrict__ out,
                             int E, int N) {
    int lane = threadIdx.x & 31;
    int warp = (blockIdx.x * blockDim.x + threadIdx.x) >> 5;
    int nwarp = (gridDim.x * blockDim.x) >> 5;

    float4 w01 = ((const float4*)Wp2)[lane * 2];
    float4 w23 = ((const float4*)Wp2)[lane * 2 + 1];
    float b0 = bp2[0], b1 = bp2[1];

    for (int e = warp; e < E; e += nwarp) {
        int s = ei[e];
        int d = ei[E + e];
        if ((unsigned)s >= (unsigned)N || (unsigned)d >= (unsigned)N) continue;
        float4 av = __ldg((const float4*)a + (size_t)s * 32 + lane);
        float4 bv = __ldg((const float4*)b + (size_t)d * 32 + lane);
        float z0 = fmaxf(av.x + bv.x, 0.f);
        float z1 = fmaxf(av.y + bv.y, 0.f);
        float z2 = fmaxf(av.z + bv.z, 0.f);
        float z3 = fmaxf(av.w + bv.w, 0.f);
        float o0 = z0 * w01.x + z1 * w01.z + z2 * w23.x + z3 * w23.z;
        float o1 = z0 * w01.y + z1 * w01.w + z2 * w23.y + z3 * w23.w;
        #pragma unroll
        for (int off = 16; off > 0; off >>= 1) {
            o0 += __shfl_xor_sync(0xffffffffu, o0, off);
            o1 += __shfl_xor_sync(0xffffffffu, o1, off);
        }
        if (lane == 0) {
            float2 rr = make_float2(o0 + b0, o1 + b1);
            *(float2*)&out[(size_t)e * 2] = rr;
        }
    }
}

// ---------------------------------------------------------------------------
extern "C" void kernel_launch(void* const* d_in, const int* in_sizes, int n_in,
                              void* d_out, int out_size) {
    const float* x    = (const float*)d_in[0];
    const int*   ei   = (const int*)d_in[1];     // int32
    const float* ea   = (const float*)d_in[2];
    const float* We1  = (const float*)d_in[3];
    const float* be1  = (const float*)d_in[4];
    const float* Wl1  = (const float*)d_in[5];
    const float* bl1  = (const float*)d_in[6];
    const float* Wr1  = (const float*)d_in[7];
    const float* br1  = (const float*)d_in[8];
    const float* We2  = (const float*)d_in[9];
    const float* be2  = (const float*)d_in[10];
    const float* Wl2  = (const float*)d_in[11];
    const float* bl2  = (const float*)d_in[12];
    const float* Wr2  = (const float*)d_in[13];
    const float* br2  = (const float*)d_in[14];
    const float* Wp1  = (const float*)d_in[15];
    const float* bp1  = (const float*)d_in[16];
    const float* Wp2  = (const float*)d_in[17];
    const float* bp2  = (const float*)d_in[18];
    float*       out  = (float*)d_out;

    const int N = in_sizes[0] / 128;
    const int E = in_sizes[2] / 32;

    __half *aggh, *eaggh, *xh, *h1h, *h2h, *Wcath, *Wpth;
    float *af, *bf, *degc, *bv1, *bv0;
    int *rowptr, *cnt, *bsum, *boff, *csr_src, *csr_eid;
    cudaGetSymbolAddress((void**)&aggh,  g_aggh);
    cudaGetSymbolAddress((void**)&eaggh, g_eaggh);
    cudaGetSymbolAddress((void**)&xh,    g_xh);
    cudaGetSymbolAddress((void**)&h1h,   g_h1h);
    cudaGetSymbolAddress((void**)&h2h,   g_h2h);
    cudaGetSymbolAddress((void**)&af,    g_af);
    cudaGetSymbolAddress((void**)&bf,    g_bf);
    cudaGetSymbolAddress((void**)&degc,  g_degc);
    cudaGetSymbolAddress((void**)&Wcath, g_Wcath);
    cudaGetSymbolAddress((void**)&Wpth,  g_Wpth);
    cudaGetSymbolAddress((void**)&bv1,   g_bv1);
    cudaGetSymbolAddress((void**)&bv0,   g_bv0);
    cudaGetSymbolAddress((void**)&rowptr, g_rowptr);
    cudaGetSymbolAddress((void**)&cnt,    g_cnt);
    cudaGetSymbolAddress((void**)&bsum,   g_bsum);
    cudaGetSymbolAddress((void**)&boff,   g_boff);
    cudaGetSymbolAddress((void**)&csr_src, g_csr_src);
    cudaGetSymbolAddress((void**)&csr_eid, g_csr_eid);

    const int nb    = (N + 511) / 512;
    const int ggrid = (N + 127) / 128;
    const int agrid = (N + 7) / 8;
    const int egrid = 2368;

    // ---- CSR build ----
    k_zero_int<<<(N + 255) / 256, 256>>>(cnt, N);
    k_hist<<<(E + 255) / 256, 256>>>(ei, cnt, E, N);
    k_scan1<<<nb, 512>>>(cnt, rowptr, bsum, N);
    k_scan2<<<1, 1024>>>(bsum, boff, nb);
    k_scan3<<<nb, 512>>>(rowptr, boff, cnt, degc, N);
    k_fill<<<(E + 255) / 256, 256>>>(ei, rowptr, cnt, csr_src, csr_eid, E, N);

    // weight prep + half(x)
    k_wprep<<<3, 128>>>(We1, be1, Wl1, bl1, br1, Wr1,
                        We2, be2, Wl2, bl2, br2, Wr2, Wp1,
                        Wcath, Wpth, bv1, bv0);
    k_xhalf<<<1184, 256>>>((const float4*)x, (uint2*)xh, N * 32);

    // ---- layer 1 ----
    k_agg_l1<<<agrid, 256>>>(x, ea, rowptr, csr_src, csr_eid, aggh, eaggh, N);
    k_gemm_f16<<<ggrid, 256>>>(aggh, eaggh, xh, Wcath, 288, 9,
                               bv0, bv1, degc, h1h, nullptr, N, 1);

    // ---- layer 2 ----
    k_agg_l2<<<agrid, 256>>>(h1h, rowptr, csr_src, aggh, N);
    k_gemm_f16<<<ggrid, 256>>>(aggh, eaggh, h1h, Wcath + 128 * 288, 288, 9,
                               bv0 + 128, bv1 + 128, degc, h2h, nullptr, N, 1);

    // ---- edge predictor (factored) ----
    k_gemm_f16<<<ggrid, 256>>>(h2h, nullptr, nullptr, Wpth, 128, 4,
                               bp1, nullptr, nullptr, nullptr, af, N, 0);
    k_gemm_f16<<<ggrid, 256>>>(h2h, nullptr, nullptr, Wpth + 128 * 128, 128, 4,
                               nullptr, nullptr, nullptr, nullptr, bf, N, 0);

    k_edge_final<<<egrid, 256>>>(af, bf, ei, Wp2, bp2, out, E, N);
}

// round 13
// speedup vs baseline: 1.3549x; 1.0078x over previous
#include <cuda_runtime.h>
#include <cuda_fp16.h>
#include <cstdint>

#define N_NODES_MAX 100000
#define N_EDGES_MAX 600000

// ---------------------------------------------------------------------------
// Scratch (device globals)
// ---------------------------------------------------------------------------
__device__ __align__(16) __half g_aggh [(size_t)N_NODES_MAX * 128];  // mean agg (half)
__device__ __align__(16) __half g_eaggh[(size_t)N_NODES_MAX * 32];   // mean edge_attr (half)
__device__ __align__(16) __half g_xh   [(size_t)N_NODES_MAX * 128];  // half(x)
__device__ __align__(16) __half g_h1h  [(size_t)N_NODES_MAX * 128];  // layer-1 out (half)
__device__ __align__(16) __half g_h2h  [(size_t)N_NODES_MAX * 128];  // layer-2 out (half)
__device__ __align__(16) float  g_af   [(size_t)N_NODES_MAX * 128];  // predictor 'a' (fp32)
__device__ __align__(16) float  g_bf   [(size_t)N_NODES_MAX * 128];  // predictor 'b' (fp32)
__device__ __align__(16) float  g_degc [N_NODES_MAX];                // deg>0 ? 1 : 0
__device__ __align__(16) __half g_Wcath[2 * 128 * 288];              // [n][Wl^T|P^T|Wr^T]
__device__ __align__(16) __half g_Wpth [2 * 128 * 128];              // Wp1a^T, Wp1b^T
__device__ __align__(16) float  g_bv1  [2 * 128];                    // be_l @ Wl_l
__device__ __align__(16) float  g_bv0  [2 * 128];                    // bl_l + br_l
// CSR
__device__ int g_rowptr[N_NODES_MAX + 1];
__device__ int g_cnt   [N_NODES_MAX];
__device__ int g_bsum  [1024];
__device__ int g_boff  [1024];
__device__ int g_csr_src[N_EDGES_MAX];
__device__ int g_csr_eid[N_EDGES_MAX];

// ---------------------------------------------------------------------------
// helpers
// ---------------------------------------------------------------------------
__device__ __forceinline__ void cp16(uint32_t dst, const void* src, int srcsize) {
    asm volatile("cp.async.ca.shared.global [%0], [%1], 16, %2;"
                 :: "r"(dst), "l"(src), "r"(srcsize) : "memory");
}
__device__ __forceinline__ void cp_commit() {
    asm volatile("cp.async.commit_group;" ::: "memory");
}
template <int N>
__device__ __forceinline__ void cp_wait() {
    asm volatile("cp.async.wait_group %0;" :: "n"(N) : "memory");
}
__device__ __forceinline__ void mma_f16(float c[4], const uint32_t a[4],
                                        uint32_t b0, uint32_t b1) {
    asm("mma.sync.aligned.m16n8k16.row.col.f32.f16.f16.f32 "
        "{%0,%1,%2,%3}, {%4,%5,%6,%7}, {%8,%9}, {%0,%1,%2,%3};"
        : "+f"(c[0]), "+f"(c[1]), "+f"(c[2]), "+f"(c[3])
        : "r"(a[0]), "r"(a[1]), "r"(a[2]), "r"(a[3]), "r"(b0), "r"(b1));
}

// ---------------------------------------------------------------------------
// CSR build
// ---------------------------------------------------------------------------
__global__ void k_zero_int(int* __restrict__ p, int n) {
    int i = blockIdx.x * blockDim.x + threadIdx.x;
    if (i < n) p[i] = 0;
}
__global__ void k_hist(const int* __restrict__ ei, int* __restrict__ cnt, int E, int N) {
    int e = blockIdx.x * blockDim.x + threadIdx.x;
    if (e < E) {
        int d = ei[E + e];
        if ((unsigned)d < (unsigned)N) atomicAdd(&cnt[d], 1);
    }
}
__global__ void k_scan1(const int* __restrict__ cnt, int* __restrict__ rowptr,
                        int* __restrict__ bsum, int N) {
    __shared__ int sm[512];
    int t = threadIdx.x, b = blockIdx.x, i = b * 512 + t;
    int v = (i < N) ? cnt[i] : 0;
    sm[t] = v;
    __syncthreads();
    #pragma unroll
    for (int off = 1; off < 512; off <<= 1) {
        int add = (t >= off) ? sm[t - off] : 0;
        __syncthreads();
        sm[t] += add;
        __syncthreads();
    }
    if (i < N) rowptr[i + 1] = sm[t];
    if (t == 511) bsum[b] = sm[511];
}
__global__ void k_scan2(const int* __restrict__ bsum, int* __restrict__ boff, int nb) {
    __shared__ int sm[1024];
    int t = threadIdx.x;
    sm[t] = (t < nb) ? bsum[t] : 0;
    __syncthreads();
    #pragma unroll
    for (int off = 1; off < 1024; off <<= 1) {
        int add = (t >= off) ? sm[t - off] : 0;
        __syncthreads();
        sm[t] += add;
        __syncthreads();
    }
    if (t < nb) boff[t] = (t == 0) ? 0 : sm[t - 1];
}
__global__ void k_scan3(int* __restrict__ rowptr, const int* __restrict__ boff,
                        int* __restrict__ cnt, float* __restrict__ degc, int N) {
    int t = threadIdx.x, b = blockIdx.x, i = b * 512 + t;
    if (i < N) {
        rowptr[i + 1] += boff[b];
        degc[i] = cnt[i] > 0 ? 1.f : 0.f;
        cnt[i] = 0;
        if (i == 0) rowptr[0] = 0;
    }
}
__global__ void k_fill(const int* __restrict__ ei, const int* __restrict__ rowptr,
                       int* __restrict__ cnt, int* __restrict__ csr_src,
                       int* __restrict__ csr_eid, int E, int N) {
    int e = blockIdx.x * blockDim.x + threadIdx.x;
    if (e < E) {
        int s = ei[e];
        int d = ei[E + e];
        if ((unsigned)d < (unsigned)N) {
            int pos = rowptr[d] + atomicAdd(&cnt[d], 1);
            csr_src[pos] = s;
            csr_eid[pos] = e;
        }
    }
}

// ---------------------------------------------------------------------------
// x -> half copy
// ---------------------------------------------------------------------------
__global__ void k_xhalf(const float4* __restrict__ x, uint2* __restrict__ xh, int n4) {
    int i = blockIdx.x * blockDim.x + threadIdx.x;
    int stride = gridDim.x * blockDim.x;
    for (; i < n4; i += stride) {
        float4 v = x[i];
        __half2 p0 = __floats2half2_rn(v.x, v.y);
        __half2 p1 = __floats2half2_rn(v.z, v.w);
        uint2 u;
        u.x = *(uint32_t*)&p0;
        u.y = *(uint32_t*)&p1;
        xh[i] = u;
    }
}

// ---------------------------------------------------------------------------
// CSR aggregation: one warp per node, fp32 accumulate, MEAN written as half.
// Layer 1: gathers half(x) + fp32 edge_attr; also mean edge_attr.
// ---------------------------------------------------------------------------
__global__ void k_agg_l1(const __half* __restrict__ xh, const float* __restrict__ ea,
                         const int* __restrict__ rowptr,
                         const int* __restrict__ csr_src, const int* __restrict__ csr_eid,
                         __half* __restrict__ aggh, __half* __restrict__ eaggh, int N) {
    int lane = threadIdx.x & 31;
    int n = (blockIdx.x * blockDim.x + threadIdx.x) >> 5;
    if (n >= N) return;
    int beg = rowptr[n], end = rowptr[n + 1];
    float inv = 1.f / fmaxf((float)(end - beg), 1.f);
    const uint2* x2 = (const uint2*)xh;
    float4 acc = make_float4(0.f, 0.f, 0.f, 0.f);
    float eacc = 0.f;
    int i = beg;
    for (; i + 1 < end; i += 2) {
        int s0 = __ldg(&csr_src[i]),     e0 = __ldg(&csr_eid[i]);
        int s1 = __ldg(&csr_src[i + 1]), e1 = __ldg(&csr_eid[i + 1]);
        uint2 u0 = __ldg(x2 + (size_t)s0 * 32 + lane);
        uint2 u1 = __ldg(x2 + (size_t)s1 * 32 + lane);
        float w0 = __ldg(&ea[(size_t)e0 * 32 + lane]);
        float w1 = __ldg(&ea[(size_t)e1 * 32 + lane]);
        float2 a0 = __half22float2(*(__half2*)&u0.x);
        float2 a1 = __half22float2(*(__half2*)&u0.y);
        float2 b0 = __half22float2(*(__half2*)&u1.x);
        float2 b1 = __half22float2(*(__half2*)&u1.y);
        acc.x += a0.x + b0.x; acc.y += a0.y + b0.y;
        acc.z += a1.x + b1.x; acc.w += a1.y + b1.y;
        eacc += w0 + w1;
    }
    if (i < end) {
        int s0 = __ldg(&csr_src[i]), e0 = __ldg(&csr_eid[i]);
        uint2 u0 = __ldg(x2 + (size_t)s0 * 32 + lane);
        float w0 = __ldg(&ea[(size_t)e0 * 32 + lane]);
        float2 a0 = __half22float2(*(__half2*)&u0.x);
        float2 a1 = __half22float2(*(__half2*)&u0.y);
        acc.x += a0.x; acc.y += a0.y; acc.z += a1.x; acc.w += a1.y;
        eacc += w0;
    }
    __half2 p0 = __floats2half2_rn(acc.x * inv, acc.y * inv);
    __half2 p1 = __floats2half2_rn(acc.z * inv, acc.w * inv);
    uint2 u;
    u.x = *(uint32_t*)&p0;
    u.y = *(uint32_t*)&p1;
    ((uint2*)aggh)[(size_t)n * 32 + lane] = u;
    eaggh[(size_t)n * 32 + lane] = __float2half_rn(eacc * inv);
}

__global__ void k_agg_l2(const __half* __restrict__ xh,
                         const int* __restrict__ rowptr,
                         const int* __restrict__ csr_src,
                         __half* __restrict__ aggh, int N) {
    int lane = threadIdx.x & 31;
    int n = (blockIdx.x * blockDim.x + threadIdx.x) >> 5;
    if (n >= N) return;
    int beg = rowptr[n], end = rowptr[n + 1];
    float inv = 1.f / fmaxf((float)(end - beg), 1.f);
    const uint2* x2 = (const uint2*)xh;
    float4 acc = make_float4(0.f, 0.f, 0.f, 0.f);
    for (int i = beg; i < end; i++) {
        int s0 = __ldg(&csr_src[i]);
        uint2 u = __ldg(x2 + (size_t)s0 * 32 + lane);
        float2 f0 = __half22float2(*(__half2*)&u.x);
        float2 f1 = __half22float2(*(__half2*)&u.y);
        acc.x += f0.x; acc.y += f0.y; acc.z += f1.x; acc.w += f1.y;
    }
    __half2 p0 = __floats2half2_rn(acc.x * inv, acc.y * inv);
    __half2 p1 = __floats2half2_rn(acc.z * inv, acc.w * inv);
    uint2 u;
    u.x = *(uint32_t*)&p0;
    u.y = *(uint32_t*)&p1;
    ((uint2*)aggh)[(size_t)n * 32 + lane] = u;
}

// ---------------------------------------------------------------------------
// Weight prep (half, transposed K-major):
// block 0/1: Wcat[l][n][0:128]=Wl^T, [128:160]=(We@Wl)^T, [160:288]=Wr^T;
//            bv1 = be@Wl, bv0 = bl+br.
// block 2:   Wpt[0]=Wp1[:128]^T, Wpt[1]=Wp1[128:]^T.
// ---------------------------------------------------------------------------
__global__ void k_wprep(const float* We1, const float* be1, const float* Wl1,
                        const float* bl1, const float* br1, const float* Wr1,
                        const float* We2, const float* be2, const float* Wl2,
                        const float* bl2, const float* br2, const float* Wr2,
                        const float* Wp1,
                        __half* Wcat, __half* Wpt, float* bv1, float* bv0) {
    int l = blockIdx.x;
    int j = threadIdx.x;
    if (l < 2) {
        const float* We = l ? We2 : We1;
        const float* be = l ? be2 : be1;
        const float* Wl = l ? Wl2 : Wl1;
        const float* bl = l ? bl2 : bl1;
        const float* br = l ? br2 : br1;
        const float* Wr = l ? Wr2 : Wr1;
        __half* row = Wcat + (size_t)l * 128 * 288 + (size_t)j * 288;
        for (int k = 0; k < 128; k++) row[k] = __float2half_rn(Wl[k * 128 + j]);
        for (int i = 0; i < 32; i++) {
            float acc = 0.f;
            for (int k = 0; k < 128; k++) acc = fmaf(We[i * 128 + k], Wl[k * 128 + j], acc);
            row[128 + i] = __float2half_rn(acc);
        }
        for (int k = 0; k < 128; k++) row[160 + k] = __float2half_rn(Wr[k * 128 + j]);
        float a1 = 0.f;
        for (int k = 0; k < 128; k++) a1 = fmaf(be[k], Wl[k * 128 + j], a1);
        bv1[l * 128 + j] = a1;
        bv0[l * 128 + j] = bl[j] + br[j];
    } else {
        __half* ra = Wpt + (size_t)j * 128;
        __half* rb = Wpt + (size_t)128 * 128 + (size_t)j * 128;
        for (int k = 0; k < 128; k++) {
            ra[k] = __float2half_rn(Wp1[k * 128 + j]);
            rb[k] = __float2half_rn(Wp1[(128 + k) * 128 + j]);
        }
    }
}

// ---------------------------------------------------------------------------
// fp16 tensor-core SAGE GEMM (mma.sync m16n8k16), cp.async double-buffered.
//   C = act( A1 @ W^T + (A2 @ P^T)? + (B @ Wr^T)? + bv0? + degc[m]*bv1? )
// BM=128, BN=128, BK=32 halves. 256 threads = 8 warps 4x2; warp = 32x64.
// smem rows padded to 20 words: frag banks (20g+q)%32 all distinct.
// blockIdx.y==1 selects alternate problem (Wt2, bv0=null, Cf2) — predictor b.
// ---------------------------------------------------------------------------
__global__ __launch_bounds__(256)
void k_gemm_f16(const __half* __restrict__ A1,
                const __half* __restrict__ A2,
                const __half* __restrict__ B,
                const __half* __restrict__ Wt, int wstride, int ktiles,
                const float* __restrict__ bv0,
                const float* __restrict__ bv1,
                const float* __restrict__ degc,
                __half* __restrict__ Ch,
                float* __restrict__ Cf,
                const __half* __restrict__ Wt2,
                float* __restrict__ Cf2,
                int M, int relu) {
    __shared__ __align__(16) uint32_t As[2][128][20];
    __shared__ __align__(16) uint32_t Bs[2][128][20];

    if (blockIdx.y == 1) { Wt = Wt2; Cf = Cf2; bv0 = nullptr; }

    const int tid    = threadIdx.x;
    const int lane   = tid & 31;
    const int warp   = tid >> 5;
    const int gid    = lane >> 2;
    const int qid    = lane & 3;
    const int warp_m = warp >> 1;
    const int warp_n = warp & 1;
    const int m0     = blockIdx.x * 128;

    float c[2][8][4];
    #pragma unroll
    for (int mt = 0; mt < 2; mt++)
        #pragma unroll
        for (int nt = 0; nt < 8; nt++)
            #pragma unroll
            for (int i = 0; i < 4; i++) c[mt][nt][i] = 0.f;

    // 512 16B-chunks per tile (A:512, B:512) -> 2 iters x 256 threads each
    auto issue_tile = [&](int t, int buf) {
        const __half* Ap;
        int astr, akb;
        if (ktiles == 4 || t < 4) { Ap = A1; astr = 128; akb = t * 32; }
        else if (t == 4)          { Ap = A2; astr = 32;  akb = 0;      }
        else                      { Ap = B;  astr = 128; akb = (t - 5) * 32; }
        const int bkb = t * 32;
        #pragma unroll
        for (int i = 0; i < 2; i++) {
            int chunk = tid + i * 256;      // 0..511
            int r = chunk >> 2, qc = chunk & 3;
            int gm = m0 + r;
            uint32_t dst = (uint32_t)__cvta_generic_to_shared(&As[buf][r][qc * 4]);
            cp16(dst, Ap + (size_t)gm * astr + akb + qc * 8, gm < M ? 16 : 0);
        }
        #pragma unroll
        for (int i = 0; i < 2; i++) {
            int chunk = tid + i * 256;      // 0..511
            int r = chunk >> 2, qc = chunk & 3;
            uint32_t dst = (uint32_t)__cvta_generic_to_shared(&Bs[buf][r][qc * 4]);
            cp16(dst, Wt + (size_t)r * wstride + bkb + qc * 8, 16);
        }
        cp_commit();
    };

    issue_tile(0, 0);
    int buf = 0;

    for (int t = 0; t < ktiles; t++) {
        const bool has_next = (t + 1 < ktiles);
        if (has_next) issue_tile(t + 1, buf ^ 1);
        if (has_next) cp_wait<1>(); else cp_wait<0>();
        __syncthreads();

        #pragma unroll
        for (int ks = 0; ks < 2; ks++) {
            const int kw = ks * 8;
            uint32_t a[2][4];
            #pragma unroll
            for (int mt = 0; mt < 2; mt++) {
                int row = warp_m * 32 + mt * 16 + gid;
                a[mt][0] = As[buf][row][kw + qid];
                a[mt][1] = As[buf][row + 8][kw + qid];
                a[mt][2] = As[buf][row][kw + qid + 4];
                a[mt][3] = As[buf][row + 8][kw + qid + 4];
            }
            #pragma unroll
            for (int nt = 0; nt < 8; nt++) {
                int n = warp_n * 64 + nt * 8 + gid;
                uint32_t b0 = Bs[buf][n][kw + qid];
                uint32_t b1 = Bs[buf][n][kw + qid + 4];
                mma_f16(c[0][nt], a[0], b0, b1);
                mma_f16(c[1][nt], a[1], b0, b1);
            }
        }
        __syncthreads();
        buf ^= 1;
    }

    // epilogue
    #pragma unroll
    for (int mt = 0; mt < 2; mt++) {
        int rbase = m0 + warp_m * 32 + mt * 16 + gid;
        #pragma unroll
        for (int h = 0; h < 2; h++) {
            int r = rbase + h * 8;
            if (r >= M) continue;
            float coef = (bv1 && degc) ? degc[r] : 0.f;
            #pragma unroll
            for (int nt = 0; nt < 8; nt++) {
                int j = warp_n * 64 + nt * 8 + qid * 2;
                float v0 = c[mt][nt][h * 2 + 0];
                float v1 = c[mt][nt][h * 2 + 1];
                if (bv0) { v0 += bv0[j]; v1 += bv0[j + 1]; }
                if (bv1) { v0 += coef * bv1[j]; v1 += coef * bv1[j + 1]; }
                if (relu) { v0 = fmaxf(v0, 0.f); v1 = fmaxf(v1, 0.f); }
                if (Ch) {
                    __half2 p = __floats2half2_rn(v0, v1);
                    *(__half2*)&Ch[(size_t)r * 128 + j] = p;
                } else {
                    *(float2*)&Cf[(size_t)r * 128 + j] = make_float2(v0, v1);
                }
            }
        }
    }
}

// ---------------------------------------------------------------------------
// Final edge predictor: out[e] = relu(a[src] + b[dst]) @ Wp2 + bp2
// 4 edges per warp, 8 lanes per edge (lane owns 16 features).
// ---------------------------------------------------------------------------
__global__ void k_edge_final(const float* __restrict__ a,
                             const float* __restrict__ b,
                             const int* __restrict__ ei,
                             const float* __restrict__ Wp2,
                             const float* __restrict__ bp2,
                             float* __restrict__ out,
                             int E, int N) {
    int lane = threadIdx.x & 31;
    int q    = lane & 7;          // feature-chunk id within edge
    int sub  = lane >> 3;         // edge id within warp (0..3)
    int warp = (blockIdx.x * blockDim.x + threadIdx.x) >> 5;
    int nwarp = (gridDim.x * blockDim.x) >> 5;

    // lane's 4 float4 feature-chunks: global chunk c = q*4+i -> rows 4c..4c+3
    float4 wA[4], wB[4];
    #pragma unroll
    for (int i = 0; i < 4; i++) {
        int c = q * 4 + i;
        wA[i] = ((const float4*)Wp2)[c * 2];
        wB[i] = ((const float4*)Wp2)[c * 2 + 1];
    }
    float b0 = bp2[0], b1 = bp2[1];

    const float4* a4 = (const float4*)a;
    const float4* b4 = (const float4*)b;

    for (int base = warp * 4; base < E; base += nwarp * 4) {
        int e = base + sub;
        bool valid = (e < E);
        float o0 = 0.f, o1 = 0.f;
        if (valid) {
            int s = ei[e];
            int d = ei[E + e];
            if ((unsigned)s < (unsigned)N && (unsigned)d < (unsigned)N) {
                float4 av[4], bv[4];
                #pragma unroll
                for (int i = 0; i < 4; i++) {
                    av[i] = __ldg(a4 + (size_t)s * 32 + q * 4 + i);
                    bv[i] = __ldg(b4 + (size_t)d * 32 + q * 4 + i);
                }
                #pragma unroll
                for (int i = 0; i < 4; i++) {
                    float z0 = fmaxf(av[i].x + bv[i].x, 0.f);
                    float z1 = fmaxf(av[i].y + bv[i].y, 0.f);
                    float z2 = fmaxf(av[i].z + bv[i].z, 0.f);
                    float z3 = fmaxf(av[i].w + bv[i].w, 0.f);
                    o0 += z0 * wA[i].x + z1 * wA[i].z + z2 * wB[i].x + z3 * wB[i].z;
                    o1 += z0 * wA[i].y + z1 * wA[i].w + z2 * wB[i].y + z3 * wB[i].w;
                }
            } else {
                valid = false;
            }
        }
        // reduce across the 8 lanes of this edge's subgroup
        #pragma unroll
        for (int off = 4; off > 0; off >>= 1) {
            o0 += __shfl_xor_sync(0xffffffffu, o0, off);
            o1 += __shfl_xor_sync(0xffffffffu, o1, off);
        }
        if (q == 0 && valid) {
            *(float2*)&out[(size_t)e * 2] = make_float2(o0 + b0, o1 + b1);
        }
    }
}

// ---------------------------------------------------------------------------
extern "C" void kernel_launch(void* const* d_in, const int* in_sizes, int n_in,
                              void* d_out, int out_size) {
    const float* x    = (const float*)d_in[0];
    const int*   ei   = (const int*)d_in[1];     // int32
    const float* ea   = (const float*)d_in[2];
    const float* We1  = (const float*)d_in[3];
    const float* be1  = (const float*)d_in[4];
    const float* Wl1  = (const float*)d_in[5];
    const float* bl1  = (const float*)d_in[6];
    const float* Wr1  = (const float*)d_in[7];
    const float* br1  = (const float*)d_in[8];
    const float* We2  = (const float*)d_in[9];
    const float* be2  = (const float*)d_in[10];
    const float* Wl2  = (const float*)d_in[11];
    const float* bl2  = (const float*)d_in[12];
    const float* Wr2  = (const float*)d_in[13];
    const float* br2  = (const float*)d_in[14];
    const float* Wp1  = (const float*)d_in[15];
    const float* bp1  = (const float*)d_in[16];
    const float* Wp2  = (const float*)d_in[17];
    const float* bp2  = (const float*)d_in[18];
    float*       out  = (float*)d_out;

    const int N = in_sizes[0] / 128;
    const int E = in_sizes[2] / 32;

    __half *aggh, *eaggh, *xh, *h1h, *h2h, *Wcath, *Wpth;
    float *af, *bf, *degc, *bv1, *bv0;
    int *rowptr, *cnt, *bsum, *boff, *csr_src, *csr_eid;
    cudaGetSymbolAddress((void**)&aggh,  g_aggh);
    cudaGetSymbolAddress((void**)&eaggh, g_eaggh);
    cudaGetSymbolAddress((void**)&xh,    g_xh);
    cudaGetSymbolAddress((void**)&h1h,   g_h1h);
    cudaGetSymbolAddress((void**)&h2h,   g_h2h);
    cudaGetSymbolAddress((void**)&af,    g_af);
    cudaGetSymbolAddress((void**)&bf,    g_bf);
    cudaGetSymbolAddress((void**)&degc,  g_degc);
    cudaGetSymbolAddress((void**)&Wcath, g_Wcath);
    cudaGetSymbolAddress((void**)&Wpth,  g_Wpth);
    cudaGetSymbolAddress((void**)&bv1,   g_bv1);
    cudaGetSymbolAddress((void**)&bv0,   g_bv0);
    cudaGetSymbolAddress((void**)&rowptr, g_rowptr);
    cudaGetSymbolAddress((void**)&cnt,    g_cnt);
    cudaGetSymbolAddress((void**)&bsum,   g_bsum);
    cudaGetSymbolAddress((void**)&boff,   g_boff);
    cudaGetSymbolAddress((void**)&csr_src, g_csr_src);
    cudaGetSymbolAddress((void**)&csr_eid, g_csr_eid);

    const int nb    = (N + 511) / 512;
    const int agrid = (N + 7) / 8;
    const int egrid = 2368;
    dim3 ggrid1((N + 127) / 128, 1);
    dim3 ggrid2((N + 127) / 128, 2);

    // ---- CSR build ----
    k_zero_int<<<(N + 255) / 256, 256>>>(cnt, N);
    k_hist<<<(E + 255) / 256, 256>>>(ei, cnt, E, N);
    k_scan1<<<nb, 512>>>(cnt, rowptr, bsum, N);
    k_scan2<<<1, 1024>>>(bsum, boff, nb);
    k_scan3<<<nb, 512>>>(rowptr, boff, cnt, degc, N);
    k_fill<<<(E + 255) / 256, 256>>>(ei, rowptr, cnt, csr_src, csr_eid, E, N);

    // weight prep + half(x)
    k_wprep<<<3, 128>>>(We1, be1, Wl1, bl1, br1, Wr1,
                        We2, be2, Wl2, bl2, br2, Wr2, Wp1,
                        Wcath, Wpth, bv1, bv0);
    k_xhalf<<<1184, 256>>>((const float4*)x, (uint2*)xh, N * 32);

    // ---- layer 1 ----
    k_agg_l1<<<agrid, 256>>>(xh, ea, rowptr, csr_src, csr_eid, aggh, eaggh, N);
    k_gemm_f16<<<ggrid1, 256>>>(aggh, eaggh, xh, Wcath, 288, 9,
                                bv0, bv1, degc, h1h, nullptr,
                                nullptr, nullptr, N, 1);

    // ---- layer 2 ----
    k_agg_l2<<<agrid, 256>>>(h1h, rowptr, csr_src, aggh, N);
    k_gemm_f16<<<ggrid1, 256>>>(aggh, eaggh, h1h, Wcath + 128 * 288, 288, 9,
                                bv0 + 128, bv1 + 128, degc, h2h, nullptr,
                                nullptr, nullptr, N, 1);

    // ---- edge predictor (factored, fused a+b via gridDim.y) ----
    k_gemm_f16<<<ggrid2, 256>>>(h2h, nullptr, nullptr, Wpth, 128, 4,
                                bp1, nullptr, nullptr, nullptr, af,
                                Wpth + 128 * 128, bf, N, 0);

    k_edge_final<<<egrid, 256>>>(af, bf, ei, Wp2, bp2, out, E, N);
}